// round 1
// baseline (speedup 1.0000x reference)
#include <cuda_runtime.h>
#include <cstdint>

#define NIMG   8
#define NANCH  25200
#define NCH    85
#define NC     80
#define MAXC   2048
#define CAPK   4096
#define DET    300
#define CONF   0.96f
#define IOUT   0.45f

// ---------------- device scratch (no allocations allowed) ----------------
__device__ int g_count[NIMG];
__device__ unsigned long long g_keys[NIMG][CAPK];

// ---------------- K0: reset ----------------
__global__ void k_reset() {
    if (threadIdx.x < NIMG) g_count[threadIdx.x] = 0;
}

// ---------------- K1: candidate extraction ----------------
// Warp-cooperative: each warp owns 32 consecutive anchors; ballot on obj>CONF,
// then the whole warp scans the 80 class scores of each passing anchor
// (coalesced). Candidates staged in smem; ONE global atomicAdd per block
// reserves space (avoids per-candidate same-address L2 atomic serialization).
__global__ void __launch_bounds__(256) k_extract(const float* __restrict__ pred) {
    const int img  = blockIdx.y;
    const int warp = threadIdx.x >> 5;
    const int lane = threadIdx.x & 31;
    const int abase = blockIdx.x * 256 + warp * 32;

    __shared__ unsigned long long sbuf[1024];
    __shared__ int sn, sbase;
    if (threadIdx.x == 0) sn = 0;
    __syncthreads();

    int a = abase + lane;
    float obj = 0.0f;
    if (a < NANCH) obj = pred[((size_t)img * NANCH + a) * NCH + 4];

    unsigned mask = __ballot_sync(0xffffffffu, obj > CONF);
    while (mask) {
        int i = __ffs(mask) - 1;
        mask &= mask - 1;
        int aa = abase + i;
        float oo = __shfl_sync(0xffffffffu, obj, i);
        const float* row = pred + ((size_t)img * NANCH + aa) * NCH;
        #pragma unroll
        for (int cc = 0; cc < 3; cc++) {
            int c = lane + cc * 32;
            if (c < NC) {
                float s = __fmul_rn(row[5 + c], oo);   // matches XLA rn mul
                if (s > CONF) {
                    // key: score desc major, flat-index asc minor (top_k tiebreak)
                    unsigned long long key =
                        ((unsigned long long)__float_as_uint(s) << 32) |
                        (unsigned long long)(0xFFFFFFFFu - (unsigned)(aa * NC + c));
                    int lp = atomicAdd(&sn, 1);
                    if (lp < 1024) sbuf[lp] = key;
                    else { // overflow (practically never): direct global push
                        int gp = atomicAdd(&g_count[img], 1);
                        if (gp < CAPK) g_keys[img][gp] = key;
                    }
                }
            }
        }
    }
    __syncthreads();
    int n = min(sn, 1024);
    if (threadIdx.x == 0) sbase = atomicAdd(&g_count[img], n);
    __syncthreads();
    for (int i = threadIdx.x; i < n; i += 256) {
        int gp = sbase + i;
        if (gp < CAPK) g_keys[img][gp] = sbuf[i];
    }
}

// ---------------- bitonic sort (descending, in smem) ----------------
__device__ __forceinline__ void bitonic_desc(unsigned long long* a, int n, int tid, int nthreads) {
    for (int k = 2; k <= n; k <<= 1) {
        for (int j = k >> 1; j > 0; j >>= 1) {
            __syncthreads();
            for (int i = tid; i < n; i += nthreads) {
                int p = i ^ j;
                if (p > i) {
                    bool up = (i & k) == 0;              // "up" blocks sort descending
                    unsigned long long x = a[i], y = a[p];
                    bool sw = up ? (x < y) : (x > y);
                    if (sw) { a[i] = y; a[p] = x; }
                }
            }
        }
    }
    __syncthreads();
}

// ---------------- exact IoU matching the reference fp32 sequence ----------------
__device__ __forceinline__ bool iou_gt(const float4 A, const float areaA, const float4 B) {
    float ltx = fmaxf(A.x, B.x), lty = fmaxf(A.y, B.y);
    float rbx = fminf(A.z, B.z), rby = fminf(A.w, B.w);
    float wx = fmaxf(__fsub_rn(rbx, ltx), 0.0f);
    float wy = fmaxf(__fsub_rn(rby, lty), 0.0f);
    float inter = __fmul_rn(wx, wy);
    float areaB = __fmul_rn(__fsub_rn(B.z, B.x), __fsub_rn(B.w, B.y));
    float denom = __fadd_rn(__fsub_rn(__fadd_rn(areaA, areaB), inter), 1e-9f);
    return __fdiv_rn(inter, denom) > IOUT;
}

// ---------------- smem layout offsets for k_nms ----------------
#define OFF_KEYS   0        // u64[4096]            32768
#define OFF_OFFB   32768    // float4[2048]         32768
#define OFF_RAWB   65536    // float4[2048]         32768
#define OFF_SC     98304    // float[2048]           8192
#define OFF_ORDER  106496   // ushort[2048]          4096
#define OFF_LAB    110592   // uchar[2048]           2048
#define OFF_KEEP   112640   // uchar[2048]           2048
#define OFF_CNT    114688   // int[80]                320
#define OFF_START  115008   // int[80]                320
#define SMEM_TOTAL 115328

// ---------------- K2: per-image sort + NMS + select (one block/image) ----------------
__global__ void __launch_bounds__(1024, 1) k_nms(const float* __restrict__ pred,
                                                 float* __restrict__ out) {
    extern __shared__ unsigned char smem[];
    unsigned long long* keys  = (unsigned long long*)(smem + OFF_KEYS);
    float4*             offb  = (float4*)(smem + OFF_OFFB);
    float4*             rawb  = (float4*)(smem + OFF_RAWB);
    float*              sc    = (float*)(smem + OFF_SC);
    unsigned short*     order = (unsigned short*)(smem + OFF_ORDER);
    unsigned char*      lab   = (unsigned char*)(smem + OFF_LAB);
    unsigned char*      keep  = (unsigned char*)(smem + OFF_KEEP);
    int*                cnt   = (int*)(smem + OFF_CNT);
    int*                start = (int*)(smem + OFF_START);

    const int img = blockIdx.x;
    const int tid = threadIdx.x;

    const int count  = g_count[img];
    const int cload  = min(count, CAPK);
    const int n1     = (count <= MAXC) ? MAXC : CAPK;   // sort only what's needed
    const int nvalid = min(count, MAXC);

    for (int i = tid; i < n1; i += 1024)
        keys[i] = (i < cload) ? g_keys[img][i] : 0ULL;
    if (tid < NC) cnt[tid] = 0;

    // sort A: global score order (== jax.lax.top_k order incl. tiebreaks)
    bitonic_desc(keys, n1, tid, 1024);

    // decode + gather boxes for the top MAXC
    for (int r = tid; r < MAXC; r += 1024) {
        if (r < nvalid) {
            unsigned long long k = keys[r];
            float s = __uint_as_float((unsigned)(k >> 32));
            unsigned flat = 0xFFFFFFFFu - (unsigned)k;
            int anchor = (int)(flat / NC);
            int l = (int)flat - anchor * NC;
            const float* row = pred + ((size_t)img * NANCH + anchor) * NCH;
            float cx = row[0], cy = row[1], w = row[2], h = row[3];
            float hw = __fmul_rn(0.5f, w), hh = __fmul_rn(0.5f, h);
            float4 rb;
            rb.x = __fsub_rn(cx, hw); rb.y = __fsub_rn(cy, hh);
            rb.z = __fadd_rn(cx, hw); rb.w = __fadd_rn(cy, hh);
            float off = __fmul_rn((float)l, 4.0f);
            float4 ob;
            ob.x = __fadd_rn(rb.x, off); ob.y = __fadd_rn(rb.y, off);
            ob.z = __fadd_rn(rb.z, off); ob.w = __fadd_rn(rb.w, off);
            rawb[r] = rb; offb[r] = ob; sc[r] = s;
            lab[r] = (unsigned char)l; keep[r] = 1;
            atomicAdd(&cnt[l], 1);
        } else {
            sc[r] = -1.0f; lab[r] = 255; keep[r] = 0;
            rawb[r] = make_float4(0.f, 0.f, 0.f, 0.f);
            offb[r] = make_float4(0.f, 0.f, 0.f, 0.f);
        }
    }
    __syncthreads();

    // sort B: group by label (asc), score desc within label, rank asc tiebreak
    for (int r = tid; r < MAXC; r += 1024) {
        unsigned long long k2 = 0ULL;
        if (r < nvalid) {
            k2 = ((unsigned long long)(255u - lab[r]) << 56) |
                 ((unsigned long long)__float_as_uint(sc[r]) << 24) |
                 (unsigned long long)(0xFFFFFFu - (unsigned)r);
        }
        keys[r] = k2;
    }
    bitonic_desc(keys, MAXC, tid, 1024);
    for (int q = tid; q < MAXC; q += 1024)
        order[q] = (unsigned short)(0xFFFFFFu - (unsigned)(keys[q] & 0xFFFFFFu));
    if (tid == 0) {
        int run = 0;
        for (int l = 0; l < NC; l++) { start[l] = run; run += cnt[l]; }
    }
    __syncthreads();

    // per-class greedy NMS (cross-class IoU is exactly 0 due to label*4 offset,
    // so this equals the reference's global sequential loop). Warp per class.
    const int warp = tid >> 5, lane = tid & 31;
    for (int l = warp; l < NC; l += 32) {
        const int b0 = start[l], kk = cnt[l];
        for (int a = 0; a < kk; a++) {
            int ra = order[b0 + a];
            if (keep[ra]) {                               // warp-uniform
                float4 A = offb[ra];
                float areaA = __fmul_rn(__fsub_rn(A.z, A.x), __fsub_rn(A.w, A.y));
                for (int b = a + 1 + lane; b < kk; b += 32) {
                    int rb_ = order[b0 + b];
                    if (keep[rb_] && iou_gt(A, areaA, offb[rb_]))
                        keep[rb_] = 0;
                }
                __syncwarp();
            }
        }
    }
    __syncthreads();

    // sort C: kept candidates by score desc (== top_k over masked scores)
    for (int r = tid; r < MAXC; r += 1024) {
        keys[r] = keep[r]
            ? (((unsigned long long)__float_as_uint(sc[r]) << 32) |
               (unsigned long long)(0xFFFFFFFFu - (unsigned)r))
            : 0ULL;
    }
    bitonic_desc(keys, MAXC, tid, 1024);

    // emit first DET rows: [x1,y1,x2,y2,score,label], zeros when exhausted
    for (int d = tid; d < DET; d += 1024) {
        float o0 = 0.f, o1 = 0.f, o2 = 0.f, o3 = 0.f, o4 = 0.f, o5 = 0.f;
        unsigned long long k = keys[d];
        if (k != 0ULL) {
            int r = (int)(0xFFFFFFFFu - (unsigned)k);
            float4 rb = rawb[r];
            o0 = rb.x; o1 = rb.y; o2 = rb.z; o3 = rb.w;
            o4 = sc[r]; o5 = (float)lab[r];
        }
        float* o = out + ((size_t)img * DET + d) * 6;
        o[0] = o0; o[1] = o1; o[2] = o2; o[3] = o3; o[4] = o4; o[5] = o5;
    }
}

// ---------------- launch ----------------
extern "C" void kernel_launch(void* const* d_in, const int* in_sizes, int n_in,
                              void* d_out, int out_size) {
    const float* pred = (const float*)d_in[0];
    float* out = (float*)d_out;

    cudaFuncSetAttribute(k_nms, cudaFuncAttributeMaxDynamicSharedMemorySize, SMEM_TOTAL);

    k_reset<<<1, 32>>>();
    dim3 g1((NANCH + 255) / 256, NIMG);
    k_extract<<<g1, 256>>>(pred);
    k_nms<<<NIMG, 1024, SMEM_TOTAL>>>(pred, out);
    (void)in_sizes; (void)n_in; (void)out_size;
}

// round 5
// speedup vs baseline: 1.0037x; 1.0037x over previous
#include <cuda_runtime.h>
#include <cstdint>

#define NIMG   8
#define NANCH  25200
#define NCH    85
#define NC     80
#define MAXC   2048
#define CAPK   4096
#define DET    300
#define CONF   0.96f
#define IOUT   0.45f

// ---------------- device scratch (no allocations allowed) ----------------
__device__ int g_count[NIMG];                 // zero-initialized at load; k_nms re-zeros
__device__ unsigned long long g_keys[NIMG][CAPK];

// ---------------- K1: candidate extraction ----------------
__global__ void __launch_bounds__(256) k_extract(const float* __restrict__ pred) {
    const int img  = blockIdx.y;
    const int warp = threadIdx.x >> 5;
    const int lane = threadIdx.x & 31;
    const int abase = blockIdx.x * 256 + warp * 32;

    __shared__ unsigned long long sbuf[1024];
    __shared__ int sn, sbase;
    if (threadIdx.x == 0) sn = 0;
    __syncthreads();

    int a = abase + lane;
    float obj = 0.0f;
    if (a < NANCH) obj = pred[((size_t)img * NANCH + a) * NCH + 4];

    unsigned mask = __ballot_sync(0xffffffffu, obj > CONF);
    while (mask) {
        int i = __ffs(mask) - 1;
        mask &= mask - 1;
        int aa = abase + i;
        float oo = __shfl_sync(0xffffffffu, obj, i);
        const float* row = pred + ((size_t)img * NANCH + aa) * NCH;
        #pragma unroll
        for (int cc = 0; cc < 3; cc++) {
            int c = lane + cc * 32;
            if (c < NC) {
                float s = __fmul_rn(row[5 + c], oo);   // matches XLA rn mul
                if (s > CONF) {
                    // key: score desc major, flat-index asc minor (top_k tiebreak)
                    unsigned long long key =
                        ((unsigned long long)__float_as_uint(s) << 32) |
                        (unsigned long long)(0xFFFFFFFFu - (unsigned)(aa * NC + c));
                    int lp = atomicAdd(&sn, 1);
                    if (lp < 1024) sbuf[lp] = key;
                    else {
                        int gp = atomicAdd(&g_count[img], 1);
                        if (gp < CAPK) g_keys[img][gp] = key;
                    }
                }
            }
        }
    }
    __syncthreads();
    int n = min(sn, 1024);
    if (threadIdx.x == 0) sbase = atomicAdd(&g_count[img], n);
    __syncthreads();
    for (int i = threadIdx.x; i < n; i += 256) {
        int gp = sbase + i;
        if (gp < CAPK) g_keys[img][gp] = sbuf[i];
    }
}

// ---------------- bitonic sort (descending, in smem) ----------------
__device__ __forceinline__ void bitonic_desc(unsigned long long* a, int n, int tid, int nthreads) {
    for (int k = 2; k <= n; k <<= 1) {
        for (int j = k >> 1; j > 0; j >>= 1) {
            __syncthreads();
            for (int i = tid; i < n; i += nthreads) {
                int p = i ^ j;
                if (p > i) {
                    bool up = (i & k) == 0;
                    unsigned long long x = a[i], y = a[p];
                    bool sw = up ? (x < y) : (x > y);
                    if (sw) { a[i] = y; a[p] = x; }
                }
            }
        }
    }
    __syncthreads();
}

// ---------------- exact IoU matching the reference fp32 sequence ----------------
__device__ __forceinline__ bool iou_gt(const float4 A, const float areaA, const float4 B) {
    float ltx = fmaxf(A.x, B.x), lty = fmaxf(A.y, B.y);
    float rbx = fminf(A.z, B.z), rby = fminf(A.w, B.w);
    float wx = fmaxf(__fsub_rn(rbx, ltx), 0.0f);
    float wy = fmaxf(__fsub_rn(rby, lty), 0.0f);
    float inter = __fmul_rn(wx, wy);
    float areaB = __fmul_rn(__fsub_rn(B.z, B.x), __fsub_rn(B.w, B.y));
    float denom = __fadd_rn(__fsub_rn(__fadd_rn(areaA, areaB), inter), 1e-9f);
    return __fdiv_rn(inter, denom) > IOUT;
}

// ---------------- smem layout for k_nms ----------------
#define OFF_KEYS   0        // u64[4096]: cand keys [0,2048), sort-C buf [2048,4096)
#define OFF_RAWB   32768    // float4[2048]
#define OFF_OFFB   65536    // float4[2048]
#define OFF_LAB    98304    // u8[2048]
#define OFF_KEEP   100352   // u8[2048]
#define OFF_CLIST  102400   // u16[2048]
#define OFF_CNT    106496   // int[80]
#define OFF_START  106816   // int[80]
#define OFF_CNT2   107136   // int[80]
#define OFF_MISC   107456   // int[16]
#define SMEM_TOTAL 107520

// ---------------- K2: per-image decode + greedy NMS + top-300 ----------------
__global__ void __launch_bounds__(1024, 1) k_nms(const float* __restrict__ pred,
                                                 float* __restrict__ out) {
    extern __shared__ unsigned char smem[];
    unsigned long long* keys  = (unsigned long long*)(smem + OFF_KEYS);
    float4*             rawb  = (float4*)(smem + OFF_RAWB);
    float4*             offb  = (float4*)(smem + OFF_OFFB);
    unsigned char*      lab   = (unsigned char*)(smem + OFF_LAB);
    unsigned char*      keep  = (unsigned char*)(smem + OFF_KEEP);
    unsigned short*     clist = (unsigned short*)(smem + OFF_CLIST);
    int*                cnt   = (int*)(smem + OFF_CNT);
    int*                start = (int*)(smem + OFF_START);
    int*                cnt2  = (int*)(smem + OFF_CNT2);
    int*                misc  = (int*)(smem + OFF_MISC);   // [0]=kept_n

    const int img = blockIdx.x;
    const int tid = threadIdx.x;

    const int count  = g_count[img];
    const int cload  = min(count, CAPK);
    const int nvalid = min(count, MAXC);

    if (tid < NC) { cnt[tid] = 0; cnt2[tid] = 0; }
    if (tid == 0) misc[0] = 0;

    if (count > MAXC) {
        // slow path (never hit on this data): sort CAPK keys for the true top-MAXC
        for (int i = tid; i < CAPK; i += 1024)
            keys[i] = (i < cload) ? g_keys[img][i] : 0ULL;
        bitonic_desc(keys, CAPK, tid, 1024);
    } else {
        for (int i = tid; i < MAXC; i += 1024)
            keys[i] = (i < cload) ? g_keys[img][i] : 0ULL;
        __syncthreads();
    }

    // decode + gather boxes; count per class
    for (int r = tid; r < MAXC; r += 1024) {
        if (r < nvalid) {
            unsigned long long k = keys[r];
            unsigned flat = 0xFFFFFFFFu - (unsigned)k;
            int anchor = (int)(flat / NC);
            int l = (int)flat - anchor * NC;
            const float* row = pred + ((size_t)img * NANCH + anchor) * NCH;
            float cx = row[0], cy = row[1], w = row[2], h = row[3];
            float hw = __fmul_rn(0.5f, w), hh = __fmul_rn(0.5f, h);
            float4 rb;
            rb.x = __fsub_rn(cx, hw); rb.y = __fsub_rn(cy, hh);
            rb.z = __fadd_rn(cx, hw); rb.w = __fadd_rn(cy, hh);
            float off = __fmul_rn((float)l, 4.0f);
            float4 ob;
            ob.x = __fadd_rn(rb.x, off); ob.y = __fadd_rn(rb.y, off);
            ob.z = __fadd_rn(rb.z, off); ob.w = __fadd_rn(rb.w, off);
            rawb[r] = rb; offb[r] = ob;
            lab[r] = (unsigned char)l; keep[r] = 1;
            atomicAdd(&cnt[l], 1);
        } else {
            lab[r] = 255; keep[r] = 0;
        }
    }
    __syncthreads();
    if (tid == 0) {
        int run = 0;
        for (int l = 0; l < NC; l++) { start[l] = run; run += cnt[l]; }
    }
    __syncthreads();
    // scatter candidate ranks into per-class lists (order within class arbitrary)
    for (int r = tid; r < nvalid; r += 1024) {
        int l = lab[r];
        int p = start[l] + atomicAdd(&cnt2[l], 1);
        clist[p] = (unsigned short)r;
    }
    __syncthreads();

    // greedy selection-NMS: warp per class; argmax over alive = reference order
    // (cross-class IoU is exactly 0 due to the label*4 offset)
    const int warp = tid >> 5, lane = tid & 31;
    for (int l = warp; l < NC; l += 32) {
        const int b0 = start[l], kk = cnt[l];
        while (true) {
            unsigned long long bkey = 0ULL; int bidx = -1;
            for (int b = lane; b < kk; b += 32) {
                int r = clist[b0 + b];
                if (keep[r] == 1) {
                    unsigned long long kcand = keys[r];
                    if (kcand > bkey) { bkey = kcand; bidx = b; }
                }
            }
            #pragma unroll
            for (int o = 16; o > 0; o >>= 1) {
                unsigned long long ok = __shfl_xor_sync(0xffffffffu, bkey, o);
                int ob = __shfl_xor_sync(0xffffffffu, bidx, o);
                if (ok > bkey) { bkey = ok; bidx = ob; }
            }
            if (bkey == 0ULL) break;
            int ra = clist[b0 + bidx];
            if (lane == 0) keep[ra] = 2;              // picked (final keep)
            __syncwarp();
            float4 A = offb[ra];
            float areaA = __fmul_rn(__fsub_rn(A.z, A.x), __fsub_rn(A.w, A.y));
            for (int b = lane; b < kk; b += 32) {
                int r = clist[b0 + b];
                if (keep[r] == 1 && iou_gt(A, areaA, offb[r]))
                    keep[r] = 0;
            }
            __syncwarp();
        }
    }
    __syncthreads();

    // compact kept candidates with sortable keys into keys[2048..]
    for (int i = tid; i < MAXC; i += 1024) keys[MAXC + i] = 0ULL;
    __syncthreads();
    for (int r = tid; r < nvalid; r += 1024) {
        if (keep[r] == 2) {
            unsigned long long k = keys[r];
            unsigned flat = 0xFFFFFFFFu - (unsigned)k;
            // (score desc, flat asc) with rank r embedded for O(1) fetch
            unsigned lo = ((0x1FFFFFu - flat) << 11) | (unsigned)r;
            int p = atomicAdd(&misc[0], 1);
            if (p < MAXC)
                keys[MAXC + p] = (k & 0xFFFFFFFF00000000ULL) | (unsigned long long)lo;
        }
    }
    __syncthreads();
    int kept_n = min(misc[0], MAXC);
    int m = 1; while (m < kept_n) m <<= 1;        // next pow2 (typically 1024)
    bitonic_desc(keys + MAXC, m, tid, 1024);

    // emit first DET rows: [x1,y1,x2,y2,score,label]; zeros when exhausted
    for (int d = tid; d < DET; d += 1024) {
        float o0 = 0.f, o1 = 0.f, o2 = 0.f, o3 = 0.f, o4 = 0.f, o5 = 0.f;
        unsigned long long k = (d < m) ? keys[MAXC + d] : 0ULL;
        if (k != 0ULL) {
            int r = (int)((unsigned)k & 0x7FFu);
            float4 rb = rawb[r];
            o0 = rb.x; o1 = rb.y; o2 = rb.z; o3 = rb.w;
            o4 = __uint_as_float((unsigned)(k >> 32));
            o5 = (float)lab[r];
        }
        float* o = out + ((size_t)img * DET + d) * 6;
        o[0] = o0; o[1] = o1; o[2] = o2; o[3] = o3; o[4] = o4; o[5] = o5;
    }

    // reset counter for the next launch/replay (globals start zeroed at load)
    __syncthreads();
    if (tid == 0) g_count[img] = 0;
}

// ---------------- launch ----------------
extern "C" void kernel_launch(void* const* d_in, const int* in_sizes, int n_in,
                              void* d_out, int out_size) {
    const float* pred = (const float*)d_in[0];
    float* out = (float*)d_out;

    cudaFuncSetAttribute(k_nms, cudaFuncAttributeMaxDynamicSharedMemorySize, SMEM_TOTAL);

    dim3 g1((NANCH + 255) / 256, NIMG);
    k_extract<<<g1, 256>>>(pred);
    k_nms<<<NIMG, 1024, SMEM_TOTAL>>>(pred, out);
    (void)in_sizes; (void)n_in; (void)out_size;
}

// round 6
// speedup vs baseline: 1.9125x; 1.9054x over previous
#include <cuda_runtime.h>
#include <cstdint>

#define NIMG   8
#define NANCH  25200
#define NCH    85
#define NC     80
#define MAXC   2048
#define CAPK   4096
#define BCAP   64
#define DET    300
#define CONF   0.96f
#define IOUT   0.45f
#define FULLM  0xffffffffu

// ---------------- device scratch (no allocations allowed) ----------------
__device__ int g_count[NIMG];                       // total candidates per image
__device__ int g_bcnt[NIMG * NC];                   // per-(img,class) bucket count
__device__ int g_kcnt[NIMG];                        // kept count per image
__device__ int g_slow[NIMG];                        // fallback flag
__device__ unsigned long long g_keys[NIMG][CAPK];   // flat list (slow path)
__device__ unsigned long long g_bucket[NIMG * NC][BCAP];
__device__ unsigned long long g_kept[NIMG][MAXC];

// ---------------- K1: candidate extraction ----------------
__global__ void __launch_bounds__(256) k_extract(const float* __restrict__ pred) {
    const int img  = blockIdx.y;
    const int warp = threadIdx.x >> 5;
    const int lane = threadIdx.x & 31;
    const int abase = blockIdx.x * 256 + warp * 32;

    __shared__ unsigned long long sbuf[1024];
    __shared__ int sn, sbase;
    if (threadIdx.x == 0) sn = 0;
    __syncthreads();

    int a = abase + lane;
    float obj = 0.0f;
    if (a < NANCH) obj = pred[((size_t)img * NANCH + a) * NCH + 4];

    unsigned mask = __ballot_sync(FULLM, obj > CONF);
    while (mask) {
        int i = __ffs(mask) - 1;
        mask &= mask - 1;
        int aa = abase + i;
        float oo = __shfl_sync(FULLM, obj, i);
        const float* row = pred + ((size_t)img * NANCH + aa) * NCH;
        #pragma unroll
        for (int cc = 0; cc < 3; cc++) {
            int c = lane + cc * 32;
            if (c < NC) {
                float s = __fmul_rn(row[5 + c], oo);   // matches XLA rn mul
                if (s > CONF) {
                    // key: score desc major, flat-index asc minor (top_k tiebreak)
                    unsigned long long key =
                        ((unsigned long long)__float_as_uint(s) << 32) |
                        (unsigned long long)(0xFFFFFFFFu - (unsigned)(aa * NC + c));
                    // per-(img,class) bucket for the parallel NMS kernel
                    int bi = img * NC + c;
                    int bp = atomicAdd(&g_bcnt[bi], 1);
                    if (bp < BCAP) g_bucket[bi][bp] = key;
                    // flat list for the (never-taken) slow path
                    int lp = atomicAdd(&sn, 1);
                    if (lp < 1024) sbuf[lp] = key;
                    else {
                        int gp = atomicAdd(&g_count[img], 1);
                        if (gp < CAPK) g_keys[img][gp] = key;
                    }
                }
            }
        }
    }
    __syncthreads();
    int n = min(sn, 1024);
    if (threadIdx.x == 0) sbase = atomicAdd(&g_count[img], n);
    __syncthreads();
    for (int i = threadIdx.x; i < n; i += 256) {
        int gp = sbase + i;
        if (gp < CAPK) g_keys[img][gp] = sbuf[i];
    }
}

// ---------------- exact IoU matching the reference fp32 sequence ----------------
__device__ __forceinline__ bool iou_gt(const float4 A, const float areaA, const float4 B) {
    float ltx = fmaxf(A.x, B.x), lty = fmaxf(A.y, B.y);
    float rbx = fminf(A.z, B.z), rby = fminf(A.w, B.w);
    float wx = fmaxf(__fsub_rn(rbx, ltx), 0.0f);
    float wy = fmaxf(__fsub_rn(rby, lty), 0.0f);
    float inter = __fmul_rn(wx, wy);
    float areaB = __fmul_rn(__fsub_rn(B.z, B.x), __fsub_rn(B.w, B.y));
    float denom = __fadd_rn(__fsub_rn(__fadd_rn(areaA, areaB), inter), 1e-9f);
    return __fdiv_rn(inter, denom) > IOUT;
}

// warp compare-exchange step for one element held in a register
__device__ __forceinline__ unsigned long long cmpswap64(unsigned long long v, int j,
                                                        bool desc, int lane) {
    unsigned long long x = __shfl_xor_sync(FULLM, v, j);
    bool lower = (lane & j) == 0;          // this lane holds the lower index of the pair
    bool takeMax = (lower == desc);
    return takeMax ? (v > x ? v : x) : (v < x ? v : x);
}

// decode key -> offset box + area (rn ops bit-match the reference)
__device__ __forceinline__ void decode_off(const float* __restrict__ pred, int img,
                                           unsigned long long key, float4* ob, float* ar) {
    unsigned flat = 0xFFFFFFFFu - (unsigned)key;
    int anchor = (int)(flat / NC);
    int l = (int)flat - anchor * NC;
    const float* row = pred + ((size_t)img * NANCH + anchor) * NCH;
    float cx = row[0], cy = row[1], w = row[2], h = row[3];
    float hw = __fmul_rn(0.5f, w), hh = __fmul_rn(0.5f, h);
    float off = __fmul_rn((float)l, 4.0f);
    ob->x = __fadd_rn(__fsub_rn(cx, hw), off);
    ob->y = __fadd_rn(__fsub_rn(cy, hh), off);
    ob->z = __fadd_rn(__fadd_rn(cx, hw), off);
    ob->w = __fadd_rn(__fadd_rn(cy, hh), off);
    *ar = __fmul_rn(__fsub_rn(ob->z, ob->x), __fsub_rn(ob->w, ob->y));
}

// ---------------- K2: warp-per-(img,class) register NMS ----------------
__global__ void __launch_bounds__(128) k_cls(const float* __restrict__ pred) {
    const int gwarp = blockIdx.x * 4 + (threadIdx.x >> 5);
    if (gwarp >= NIMG * NC) return;
    const int img  = gwarp / NC;
    const int lane = threadIdx.x & 31;

    const int count = g_count[img];
    const int kk = g_bcnt[gwarp];
    if (kk > BCAP) { if (lane == 0) g_slow[img] = 1; return; }
    if (count > MAXC) return;                // slow path owns this image
    if (kk == 0) return;

    // load keys (pad 0)
    unsigned long long v0 = (lane      < kk) ? g_bucket[gwarp][lane]      : 0ULL;
    unsigned long long v1 = (lane + 32 < kk) ? g_bucket[gwarp][lane + 32] : 0ULL;

    // 64-element descending bitonic sort in registers
    #pragma unroll
    for (int k = 2; k <= 64; k <<= 1) {
        #pragma unroll
        for (int j = k >> 1; j > 0; j >>= 1) {
            if (j >= 32) {                           // only k==64, j==32: cross-reg, desc
                unsigned long long a = v0 > v1 ? v0 : v1;
                unsigned long long b = v0 > v1 ? v1 : v0;
                v0 = a; v1 = b;
            } else {
                bool descA = ((lane & k) == 0);
                bool descB = (((lane + 32) & k) == 0);
                v0 = cmpswap64(v0, j, descA, lane);
                v1 = cmpswap64(v1, j, descB, lane);
            }
        }
    }
    // indices 0..kk-1 now hold real keys sorted (score desc, flat asc)

    float4 ob0 = make_float4(0.f,0.f,0.f,0.f), ob1 = ob0;
    float ar0 = 0.f, ar1 = 0.f;
    if (lane      < kk) decode_off(pred, img, v0, &ob0, &ar0);
    if (lane + 32 < kk) decode_off(pred, img, v1, &ob1, &ar1);

    // suppression masks: bit t of m_i set if t>i and IoU(i,t)>thr
    unsigned long long m0 = 0ULL, m1 = 0ULL;
    for (int t = 0; t < kk; t++) {
        int sl = t & 31;
        float4 B;
        if (t >= 32) {                              // uniform branch
            B.x = __shfl_sync(FULLM, ob1.x, sl); B.y = __shfl_sync(FULLM, ob1.y, sl);
            B.z = __shfl_sync(FULLM, ob1.z, sl); B.w = __shfl_sync(FULLM, ob1.w, sl);
        } else {
            B.x = __shfl_sync(FULLM, ob0.x, sl); B.y = __shfl_sync(FULLM, ob0.y, sl);
            B.z = __shfl_sync(FULLM, ob0.z, sl); B.w = __shfl_sync(FULLM, ob0.w, sl);
        }
        if (lane < t && lane < kk && iou_gt(ob0, ar0, B))
            m0 |= 1ULL << t;
        if (lane + 32 < t && iou_gt(ob1, ar1, B))
            m1 |= 1ULL << t;
    }

    // serial greedy bit-clear (all lanes redundantly, no divergence)
    unsigned long long alive = (kk >= 64) ? ~0ULL : ((1ULL << kk) - 1ULL);
    for (int t = 0; t < kk; t++) {
        unsigned long long mt = __shfl_sync(FULLM, (t >= 32) ? m1 : m0, t & 31);
        if ((alive >> t) & 1ULL) alive &= ~mt;
    }

    // compact kept keys to g_kept[img]
    bool k0 = (lane      < kk) && ((alive >> lane) & 1ULL);
    bool k1 = (lane + 32 < kk) && ((alive >> (lane + 32)) & 1ULL);
    unsigned b0 = __ballot_sync(FULLM, k0);
    unsigned b1 = __ballot_sync(FULLM, k1);
    int tot = __popc(b0) + __popc(b1);
    int base = 0;
    if (lane == 0 && tot) base = atomicAdd(&g_kcnt[img], tot);
    base = __shfl_sync(FULLM, base, 0);
    unsigned lt = (1u << lane) - 1u;
    if (k0) { int p = base + __popc(b0 & lt);               if (p < MAXC) g_kept[img][p] = v0; }
    if (k1) { int p = base + __popc(b0) + __popc(b1 & lt);  if (p < MAXC) g_kept[img][p] = v1; }
}

// ---------------- block bitonic (descending, smem) ----------------
__device__ __forceinline__ void bitonic_desc(unsigned long long* a, int n, int tid, int nthreads) {
    for (int k = 2; k <= n; k <<= 1) {
        for (int j = k >> 1; j > 0; j >>= 1) {
            __syncthreads();
            for (int i = tid; i < n; i += nthreads) {
                int p = i ^ j;
                if (p > i) {
                    bool up = (i & k) == 0;
                    unsigned long long x = a[i], y = a[p];
                    bool sw = up ? (x < y) : (x > y);
                    if (sw) { a[i] = y; a[p] = x; }
                }
            }
        }
    }
    __syncthreads();
}

// ---------------- smem layout for k_final (sized for the slow path) ----------------
#define OFF_KEYS   0        // u64[4096]
#define OFF_RAWB   32768    // float4[2048]
#define OFF_OFFB   65536    // float4[2048]
#define OFF_LAB    98304    // u8[2048]
#define OFF_KEEP   100352   // u8[2048]
#define OFF_CLIST  102400   // u16[2048]
#define OFF_CNT    106496   // int[80]
#define OFF_START  106816   // int[80]
#define OFF_CNT2   107136   // int[80]
#define OFF_MISC   107456   // int[16]
#define SMEM_TOTAL 107520

// ---------------- K3: per-image final sort + emit (+ slow-path fallback) ----------------
__global__ void __launch_bounds__(1024, 1) k_final(const float* __restrict__ pred,
                                                   float* __restrict__ out) {
    extern __shared__ unsigned char smem[];
    unsigned long long* keys  = (unsigned long long*)(smem + OFF_KEYS);

    const int img = blockIdx.x;
    const int tid = threadIdx.x;
    const int count = g_count[img];
    const bool slow = (count > MAXC) || (g_slow[img] != 0);

    if (!slow) {
        // ---------------- fast path ----------------
        const int n = min(g_kcnt[img], MAXC);
        int m = 1; while (m < n) m <<= 1;
        for (int i = tid; i < m; i += 1024)
            keys[i] = (i < n) ? g_kept[img][i] : 0ULL;
        __syncthreads();
        bitonic_desc(keys, m, tid, 1024);

        for (int d = tid; d < DET; d += 1024) {
            float o0=0.f,o1=0.f,o2=0.f,o3=0.f,o4=0.f,o5=0.f;
            unsigned long long k = (d < m) ? keys[d] : 0ULL;
            if (k != 0ULL) {
                unsigned flat = 0xFFFFFFFFu - (unsigned)k;
                int anchor = (int)(flat / NC);
                int l = (int)flat - anchor * NC;
                const float* row = pred + ((size_t)img * NANCH + anchor) * NCH;
                float cx = row[0], cy = row[1], w = row[2], h = row[3];
                float hw = __fmul_rn(0.5f, w), hh = __fmul_rn(0.5f, h);
                o0 = __fsub_rn(cx, hw); o1 = __fsub_rn(cy, hh);
                o2 = __fadd_rn(cx, hw); o3 = __fadd_rn(cy, hh);
                o4 = __uint_as_float((unsigned)(k >> 32));
                o5 = (float)l;
            }
            float* o = out + ((size_t)img * DET + d) * 6;
            o[0]=o0; o[1]=o1; o[2]=o2; o[3]=o3; o[4]=o4; o[5]=o5;
        }
    } else {
        // ---------------- slow path: full R5 pipeline (statistically never taken) ----
        float4*         rawb  = (float4*)(smem + OFF_RAWB);
        float4*         offb  = (float4*)(smem + OFF_OFFB);
        unsigned char*  lab   = (unsigned char*)(smem + OFF_LAB);
        unsigned char*  keep  = (unsigned char*)(smem + OFF_KEEP);
        unsigned short* clist = (unsigned short*)(smem + OFF_CLIST);
        int*            cnt   = (int*)(smem + OFF_CNT);
        int*            start = (int*)(smem + OFF_START);
        int*            cnt2  = (int*)(smem + OFF_CNT2);
        int*            misc  = (int*)(smem + OFF_MISC);

        const int cload  = min(count, CAPK);
        const int nvalid = min(count, MAXC);
        if (tid < NC) { cnt[tid] = 0; cnt2[tid] = 0; }
        if (tid == 0) misc[0] = 0;
        for (int i = tid; i < CAPK; i += 1024)
            keys[i] = (i < cload) ? g_keys[img][i] : 0ULL;
        bitonic_desc(keys, CAPK, tid, 1024);

        for (int r = tid; r < MAXC; r += 1024) {
            if (r < nvalid) {
                unsigned long long k = keys[r];
                unsigned flat = 0xFFFFFFFFu - (unsigned)k;
                int anchor = (int)(flat / NC);
                int l = (int)flat - anchor * NC;
                const float* row = pred + ((size_t)img * NANCH + anchor) * NCH;
                float cx = row[0], cy = row[1], w = row[2], h = row[3];
                float hw = __fmul_rn(0.5f, w), hh = __fmul_rn(0.5f, h);
                float4 rb;
                rb.x = __fsub_rn(cx, hw); rb.y = __fsub_rn(cy, hh);
                rb.z = __fadd_rn(cx, hw); rb.w = __fadd_rn(cy, hh);
                float off = __fmul_rn((float)l, 4.0f);
                float4 ob;
                ob.x = __fadd_rn(rb.x, off); ob.y = __fadd_rn(rb.y, off);
                ob.z = __fadd_rn(rb.z, off); ob.w = __fadd_rn(rb.w, off);
                rawb[r] = rb; offb[r] = ob;
                lab[r] = (unsigned char)l; keep[r] = 1;
                atomicAdd(&cnt[l], 1);
            } else { lab[r] = 255; keep[r] = 0; }
        }
        __syncthreads();
        if (tid == 0) { int run = 0; for (int l = 0; l < NC; l++) { start[l] = run; run += cnt[l]; } }
        __syncthreads();
        for (int r = tid; r < nvalid; r += 1024) {
            int l = lab[r];
            int p = start[l] + atomicAdd(&cnt2[l], 1);
            clist[p] = (unsigned short)r;
        }
        __syncthreads();

        const int warp = tid >> 5, lane = tid & 31;
        for (int l = warp; l < NC; l += 32) {
            const int b0 = start[l], kk = cnt[l];
            while (true) {
                unsigned long long bkey = 0ULL; int bidx = -1;
                for (int b = lane; b < kk; b += 32) {
                    int r = clist[b0 + b];
                    if (keep[r] == 1) {
                        unsigned long long kc = keys[r];
                        if (kc > bkey) { bkey = kc; bidx = b; }
                    }
                }
                #pragma unroll
                for (int o = 16; o > 0; o >>= 1) {
                    unsigned long long ok = __shfl_xor_sync(FULLM, bkey, o);
                    int ob = __shfl_xor_sync(FULLM, bidx, o);
                    if (ok > bkey) { bkey = ok; bidx = ob; }
                }
                if (bkey == 0ULL) break;
                int ra = clist[b0 + bidx];
                if (lane == 0) keep[ra] = 2;
                __syncwarp();
                float4 A = offb[ra];
                float areaA = __fmul_rn(__fsub_rn(A.z, A.x), __fsub_rn(A.w, A.y));
                for (int b = lane; b < kk; b += 32) {
                    int r = clist[b0 + b];
                    if (keep[r] == 1 && iou_gt(A, areaA, offb[r])) keep[r] = 0;
                }
                __syncwarp();
            }
        }
        __syncthreads();
        for (int i = tid; i < MAXC; i += 1024) keys[MAXC + i] = 0ULL;
        __syncthreads();
        for (int r = tid; r < nvalid; r += 1024) {
            if (keep[r] == 2) {
                unsigned long long k = keys[r];
                unsigned flat = 0xFFFFFFFFu - (unsigned)k;
                unsigned lo = ((0x1FFFFFu - flat) << 11) | (unsigned)r;
                int p = atomicAdd(&misc[0], 1);
                if (p < MAXC)
                    keys[MAXC + p] = (k & 0xFFFFFFFF00000000ULL) | (unsigned long long)lo;
            }
        }
        __syncthreads();
        int kept_n = min(misc[0], MAXC);
        int m = 1; while (m < kept_n) m <<= 1;
        bitonic_desc(keys + MAXC, m, tid, 1024);
        for (int d = tid; d < DET; d += 1024) {
            float o0=0.f,o1=0.f,o2=0.f,o3=0.f,o4=0.f,o5=0.f;
            unsigned long long k = (d < m) ? keys[MAXC + d] : 0ULL;
            if (k != 0ULL) {
                int r = (int)((unsigned)k & 0x7FFu);
                float4 rb = rawb[r];
                o0 = rb.x; o1 = rb.y; o2 = rb.z; o3 = rb.w;
                o4 = __uint_as_float((unsigned)(k >> 32));
                o5 = (float)lab[r];
            }
            float* o = out + ((size_t)img * DET + d) * 6;
            o[0]=o0; o[1]=o1; o[2]=o2; o[3]=o3; o[4]=o4; o[5]=o5;
        }
    }

    // reset all per-image counters for the next launch / graph replay
    __syncthreads();
    if (tid == 0) { g_count[img] = 0; g_kcnt[img] = 0; g_slow[img] = 0; }
    if (tid < NC) g_bcnt[img * NC + tid] = 0;
}

// ---------------- launch ----------------
extern "C" void kernel_launch(void* const* d_in, const int* in_sizes, int n_in,
                              void* d_out, int out_size) {
    const float* pred = (const float*)d_in[0];
    float* out = (float*)d_out;

    cudaFuncSetAttribute(k_final, cudaFuncAttributeMaxDynamicSharedMemorySize, SMEM_TOTAL);

    dim3 g1((NANCH + 255) / 256, NIMG);
    k_extract<<<g1, 256>>>(pred);
    k_cls<<<(NIMG * NC + 3) / 4, 128>>>(pred);
    k_final<<<NIMG, 1024, SMEM_TOTAL>>>(pred, out);
    (void)in_sizes; (void)n_in; (void)out_size;
}